// round 3
// baseline (speedup 1.0000x reference)
#include <cuda_runtime.h>
#include <math.h>

#define B_N   4
#define C_IN  64
#define C_OUT 64
#define H_IN  128
#define W_IN  128
#define H_OUT 126
#define W_OUT 126
#define CK    576            // 9 * 64
#define HWIN  (H_IN * W_IN)
#define HWOUT (H_OUT * W_OUT)

// ---------------- scratch (device globals; no allocations allowed) ----------------
__device__ __align__(16) float g_xnhwc[B_N * HWIN * C_IN];        // 16 MB
__device__ __align__(16) float g_off[B_N * 27 * HWOUT];           // ~6.9 MB
__device__ __align__(16) float g_wT[CK * C_OUT];                  // [k*64+c][o]
__device__ __align__(16) float g_wOffT[CK * 27];                  // [k*64+c][co]

// ---------------- prep: NCHW -> NHWC transpose ----------------
__global__ void k_transpose_x(const float* __restrict__ x) {
    __shared__ float tile[32][33];
    int b   = blockIdx.z;
    int hw0 = blockIdx.x * 32;
    int c0  = blockIdx.y * 32;
    int tx = threadIdx.x, ty = threadIdx.y;
#pragma unroll
    for (int i = ty; i < 32; i += 8)
        tile[i][tx] = x[((size_t)(b * C_IN + c0 + i)) * HWIN + hw0 + tx];
    __syncthreads();
#pragma unroll
    for (int i = ty; i < 32; i += 8)
        g_xnhwc[((size_t)b * HWIN + hw0 + i) * C_IN + c0 + tx] = tile[tx][i];
}

// ---------------- prep: weight transposes to ck-major (ck = k*64 + c) ----------------
__global__ void k_prep_w(const float* __restrict__ w_off, const float* __restrict__ weight) {
    int t = blockIdx.x * blockDim.x + threadIdx.x;
    if (t < CK * 27) {
        int ck = t / 27, co = t - ck * 27;
        int kk = ck >> 6, cc = ck & 63;
        g_wOffT[t] = w_off[co * CK + cc * 9 + kk];
    }
    if (t < CK * C_OUT) {
        int ck = t >> 6, o = t & 63;
        int kk = ck >> 6, cc = ck & 63;
        g_wT[t] = weight[o * CK + cc * 9 + kk];
    }
}

// ---------------- offset conv: x (NHWC) * w_off -> g_off (sigmoid on ch 18..26) ----------------
#define A_PITCH 65
#define A_ROWS  18
#define A_COLS  34
#define A_NPIX  (A_ROWS * A_COLS)          // 612
#define SMEM_A  ((A_NPIX * A_PITCH + CK * 27) * 4)   // 221328 bytes

__global__ __launch_bounds__(256, 1) void k_offset_conv(const float* __restrict__ b_off) {
    extern __shared__ float sm[];
    float* patch = sm;                       // [612][65]
    float* ws    = sm + A_NPIX * A_PITCH;    // [576][27]

    int b  = blockIdx.z;
    int h0 = blockIdx.y * 16;
    int w0 = blockIdx.x * 32;
    int t  = threadIdx.x;

    for (int i = t; i < CK * 27; i += 256) ws[i] = g_wOffT[i];

    const float* xb = g_xnhwc + (size_t)b * HWIN * C_IN;
    for (int i = t; i < A_NPIX * C_IN; i += 256) {
        int c = i & 63, pix = i >> 6;
        int r = pix / A_COLS, col = pix - r * A_COLS;
        int hh = min(h0 + r,   H_IN - 1);
        int ww = min(w0 + col, W_IN - 1);
        patch[pix * A_PITCH + c] = xb[(hh * W_IN + ww) * C_IN + c];
    }
    __syncthreads();

    int tx = t & 31, ty = t >> 5;            // 8 rows x 32 cols, 2 pixels/thread
    float acc0[27], acc1[27];
#pragma unroll
    for (int j = 0; j < 27; j++) { acc0[j] = 0.f; acc1[j] = 0.f; }

#pragma unroll
    for (int ky = 0; ky < 3; ky++) {
#pragma unroll
        for (int kx = 0; kx < 3; kx++) {
            int kk = ky * 3 + kx;
            const float* p0 = &patch[((ty + ky)     * A_COLS + tx + kx) * A_PITCH];
            const float* p1 = &patch[((ty + 8 + ky) * A_COLS + tx + kx) * A_PITCH];
            const float* wb = &ws[kk * 64 * 27];
#pragma unroll 2
            for (int c = 0; c < 64; c++) {
                float x0 = p0[c], x1 = p1[c];
                const float* wv = wb + c * 27;
#pragma unroll
                for (int j = 0; j < 27; j++) {
                    float w = wv[j];
                    acc0[j] += x0 * w;
                    acc1[j] += x1 * w;
                }
            }
        }
    }

    int wo = w0 + tx;
    if (wo < W_OUT) {
        int ho0 = h0 + ty, ho1 = h0 + ty + 8;
        if (ho0 < H_OUT) {
#pragma unroll
            for (int j = 0; j < 27; j++) {
                float v = acc0[j] + b_off[j];
                if (j >= 18) v = 1.f / (1.f + expf(-v));
                g_off[((size_t)(b * 27 + j) * H_OUT + ho0) * W_OUT + wo] = v;
            }
        }
        if (ho1 < H_OUT) {
#pragma unroll
            for (int j = 0; j < 27; j++) {
                float v = acc1[j] + b_off[j];
                if (j >= 18) v = 1.f / (1.f + expf(-v));
                g_off[((size_t)(b * 27 + j) * H_OUT + ho1) * W_OUT + wo] = v;
            }
        }
    }
}

// ---------------- fused deform-sample + GEMM + bias + ReLU ----------------
// Block: 256 threads, tile = 32 pixels (along wo) x 64 out channels.
#define S_PITCH 584          // 576 + 8 pad: keeps p-strided LDS on distinct banks, 16B aligned
#define SMEM_B  ((32 * S_PITCH + 64 * 64 + 288 * 5) * 4)   // 96896 bytes

__global__ __launch_bounds__(256, 2) void k_deform_gemm(const float* __restrict__ bias,
                                                        float* __restrict__ out) {
    extern __shared__ float sm[];
    float* S   = sm;                         // [32][584]
    float* Wc  = sm + 32 * S_PITCH;          // [64][64] weight chunk
    float* twy = Wc + 64 * 64;
    float* twx = twy + 288;
    float* tm  = twx + 288;
    int*   ty0 = (int*)(tm + 288);
    int*   tx0 = ty0 + 288;

    int b   = blockIdx.z;
    int ho  = blockIdx.y;
    int wo0 = blockIdx.x * 32;
    int npx = min(32, W_OUT - wo0);
    int t   = threadIdx.x;

    // ---- phase 1: tap parameters (32 pixels x 9 taps) ----
    for (int j = t; j < 288; j += 256) {
        int p = j / 9, k = j - p * 9;
        float m = 0.f, wy = 0.f, wx = 0.f;
        int y0 = -5, x0 = -5;
        if (p < npx) {
            int wo = wo0 + p;
            size_t base = ((size_t)(b * 27) * H_OUT + ho) * W_OUT + wo;
            // interleaved layout: off_y[k] = ch 2k, off_x[k] = ch 2k+1
            float oy = g_off[base + (size_t)(2 * k)     * HWOUT];
            float ox = g_off[base + (size_t)(2 * k + 1) * HWOUT];
            m        = g_off[base + (size_t)(18 + k)    * HWOUT];
            int kh = k / 3, kw = k - kh * 3;
            float ys = (float)(ho + kh) + oy;
            float xs = (float)(wo + kw) + ox;
            float yf = floorf(ys), xf = floorf(xs);
            wy = ys - yf; wx = xs - xf;
            y0 = (int)yf; x0 = (int)xf;
        }
        ty0[j] = y0; tx0[j] = x0; twy[j] = wy; twx[j] = wx; tm[j] = m;
    }
    __syncthreads();

    // ---- phase 2: bilinear sampling into S[p][k*64 + c], float4 over c ----
    const float* xb = g_xnhwc + (size_t)b * HWIN * C_IN;
    for (int j = t; j < 288 * 16; j += 256) {
        int tap = j >> 4;
        int cq  = (j & 15) << 2;
        int y0 = ty0[tap], x0 = tx0[tap];
        float wy = twy[tap], wx = twx[tap], m = tm[tap];
        float w00 = (1.f - wy) * (1.f - wx) * m;
        float w01 = (1.f - wy) * wx * m;
        float w10 = wy * (1.f - wx) * m;
        float w11 = wy * wx * m;
        int y1 = y0 + 1, x1 = x0 + 1;
        bool vy0 = (unsigned)y0 < (unsigned)H_IN;
        bool vy1 = (unsigned)y1 < (unsigned)H_IN;
        bool vx0 = (unsigned)x0 < (unsigned)W_IN;
        bool vx1 = (unsigned)x1 < (unsigned)W_IN;
        float4 r = make_float4(0.f, 0.f, 0.f, 0.f);
        if (vy0) {
            const float* row = xb + (size_t)y0 * W_IN * C_IN + cq;
            if (vx0) { float4 v = *(const float4*)(row + x0 * C_IN);
                       r.x += w00 * v.x; r.y += w00 * v.y; r.z += w00 * v.z; r.w += w00 * v.w; }
            if (vx1) { float4 v = *(const float4*)(row + x1 * C_IN);
                       r.x += w01 * v.x; r.y += w01 * v.y; r.z += w01 * v.z; r.w += w01 * v.w; }
        }
        if (vy1) {
            const float* row = xb + (size_t)y1 * W_IN * C_IN + cq;
            if (vx0) { float4 v = *(const float4*)(row + x0 * C_IN);
                       r.x += w10 * v.x; r.y += w10 * v.y; r.z += w10 * v.z; r.w += w10 * v.w; }
            if (vx1) { float4 v = *(const float4*)(row + x1 * C_IN);
                       r.x += w11 * v.x; r.y += w11 * v.y; r.z += w11 * v.z; r.w += w11 * v.w; }
        }
        int p = tap / 9, k = tap - p * 9;
        *(float4*)&S[p * S_PITCH + k * 64 + cq] = r;
    }
    __syncthreads();

    // ---- phase 3: GEMM  out[p][o] = sum_ck S[p][ck] * Wt[ck][o] ----
    int og = t & 7;            // output channel group: o = og*8 + jj (contiguous -> float4 W loads)
    int p  = t >> 3;           // pixel 0..31
    float acc[8];
#pragma unroll
    for (int jj = 0; jj < 8; jj++) acc[jj] = 0.f;
    const float* Sp = &S[p * S_PITCH];

    for (int kk = 0; kk < 9; kk++) {
        for (int i = t; i < 64 * 64; i += 256) Wc[i] = g_wT[kk * 64 * 64 + i];
        __syncthreads();
        const float* Sk = Sp + kk * 64;
#pragma unroll
        for (int c4 = 0; c4 < 16; c4++) {
            float4 s4 = *(const float4*)(Sk + c4 * 4);
            float sv[4] = { s4.x, s4.y, s4.z, s4.w };
#pragma unroll
            for (int u = 0; u < 4; u++) {
                const float* wr = Wc + (c4 * 4 + u) * 64 + (og << 3);
                float4 wa = *(const float4*)(wr);
                float4 wb = *(const float4*)(wr + 4);
                acc[0] += sv[u] * wa.x; acc[1] += sv[u] * wa.y;
                acc[2] += sv[u] * wa.z; acc[3] += sv[u] * wa.w;
                acc[4] += sv[u] * wb.x; acc[5] += sv[u] * wb.y;
                acc[6] += sv[u] * wb.z; acc[7] += sv[u] * wb.w;
            }
        }
        __syncthreads();
    }

    // ---- epilogue: stage to smem for coalesced stores, + bias + ReLU ----
    float* outS = S;           // reuse (64 x 33)
#pragma unroll
    for (int jj = 0; jj < 8; jj++) outS[((og << 3) + jj) * 33 + p] = acc[jj];
    __syncthreads();
    for (int i = t; i < 64 * 32; i += 256) {
        int o = i >> 5, pp = i & 31;
        if (pp < npx) {
            float v = outS[o * 33 + pp] + bias[o];
            out[(((size_t)b * C_OUT + o) * H_OUT + ho) * W_OUT + wo0 + pp] = fmaxf(v, 0.f);
        }
    }
}

// ---------------- launch ----------------
extern "C" void kernel_launch(void* const* d_in, const int* in_sizes, int n_in,
                              void* d_out, int out_size) {
    const float* x      = (const float*)d_in[0];
    const float* w_off  = (const float*)d_in[1];
    const float* b_off  = (const float*)d_in[2];
    const float* weight = (const float*)d_in[3];
    const float* bias   = (const float*)d_in[4];
    float* out = (float*)d_out;
    (void)in_sizes; (void)n_in; (void)out_size;

    cudaFuncSetAttribute(k_offset_conv, cudaFuncAttributeMaxDynamicSharedMemorySize, SMEM_A);
    cudaFuncSetAttribute(k_deform_gemm, cudaFuncAttributeMaxDynamicSharedMemorySize, SMEM_B);

    k_transpose_x<<<dim3(HWIN / 32, C_IN / 32, B_N), dim3(32, 8)>>>(x);
    k_prep_w<<<(CK * C_OUT + 255) / 256, 256>>>(w_off, weight);
    k_offset_conv<<<dim3(4, 8, B_N), 256, SMEM_A>>>(b_off);
    k_deform_gemm<<<dim3(4, H_OUT, B_N), 256, SMEM_B>>>(bias, out);
}

// round 4
// speedup vs baseline: 2.4110x; 2.4110x over previous
#include <cuda_runtime.h>
#include <math.h>

#define B_N   4
#define C_IN  64
#define C_OUT 64
#define H_IN  128
#define W_IN  128
#define H_OUT 126
#define W_OUT 126
#define CK    576            // 9 * 64
#define HWIN  (H_IN * W_IN)
#define HWOUT (H_OUT * W_OUT)

// ---------------- scratch (device globals; no allocations allowed) ----------------
__device__ __align__(16) float g_xnhwc[B_N * HWIN * C_IN];        // 16 MB
__device__ __align__(16) float g_off[B_N * 27 * HWOUT];           // ~6.9 MB
__device__ __align__(16) float g_wT[CK * C_OUT];                  // [k*64+c][o]
__device__ __align__(16) float g_wOffT[CK * 27];                  // [k*64+c][co]

// ---------------- prep: NCHW -> NHWC transpose ----------------
__global__ void k_transpose_x(const float* __restrict__ x) {
    __shared__ float tile[32][33];
    int b   = blockIdx.z;
    int hw0 = blockIdx.x * 32;
    int c0  = blockIdx.y * 32;
    int tx = threadIdx.x, ty = threadIdx.y;
#pragma unroll
    for (int i = ty; i < 32; i += 8)
        tile[i][tx] = x[((size_t)(b * C_IN + c0 + i)) * HWIN + hw0 + tx];
    __syncthreads();
#pragma unroll
    for (int i = ty; i < 32; i += 8)
        g_xnhwc[((size_t)b * HWIN + hw0 + i) * C_IN + c0 + tx] = tile[tx][i];
}

// ---------------- prep: weight transposes to ck-major (ck = k*64 + c) ----------------
__global__ void k_prep_w(const float* __restrict__ w_off, const float* __restrict__ weight) {
    int t = blockIdx.x * blockDim.x + threadIdx.x;
    if (t < CK * 27) {
        int ck = t / 27, co = t - ck * 27;
        int kk = ck >> 6, cc = ck & 63;
        g_wOffT[t] = w_off[co * CK + cc * 9 + kk];
    }
    if (t < CK * C_OUT) {
        int ck = t >> 6, o = t & 63;
        int kk = ck >> 6, cc = ck & 63;
        g_wT[t] = weight[o * CK + cc * 9 + kk];
    }
}

// ---------------- offset conv: x (NHWC) * w_off -> g_off (sigmoid on ch 18..26) ----------------
#define A_PITCH 65
#define A_ROWS  18
#define A_COLS  34
#define A_NPIX  (A_ROWS * A_COLS)          // 612
#define SMEM_A  ((A_NPIX * A_PITCH + CK * 27) * 4)   // 221328 bytes

__global__ __launch_bounds__(256, 1) void k_offset_conv(const float* __restrict__ b_off) {
    extern __shared__ float sm[];
    float* patch = sm;                       // [612][65]
    float* ws    = sm + A_NPIX * A_PITCH;    // [576][27]

    int b  = blockIdx.z;
    int h0 = blockIdx.y * 16;
    int w0 = blockIdx.x * 32;
    int t  = threadIdx.x;

    for (int i = t; i < CK * 27; i += 256) ws[i] = g_wOffT[i];

    const float* xb = g_xnhwc + (size_t)b * HWIN * C_IN;
    for (int i = t; i < A_NPIX * C_IN; i += 256) {
        int c = i & 63, pix = i >> 6;
        int r = pix / A_COLS, col = pix - r * A_COLS;
        int hh = min(h0 + r,   H_IN - 1);
        int ww = min(w0 + col, W_IN - 1);
        patch[pix * A_PITCH + c] = xb[(hh * W_IN + ww) * C_IN + c];
    }
    __syncthreads();

    int tx = t & 31, ty = t >> 5;            // 8 rows x 32 cols, 2 pixels/thread
    float acc0[27], acc1[27];
#pragma unroll
    for (int j = 0; j < 27; j++) { acc0[j] = 0.f; acc1[j] = 0.f; }

#pragma unroll
    for (int ky = 0; ky < 3; ky++) {
#pragma unroll
        for (int kx = 0; kx < 3; kx++) {
            int kk = ky * 3 + kx;
            const float* p0 = &patch[((ty + ky)     * A_COLS + tx + kx) * A_PITCH];
            const float* p1 = &patch[((ty + 8 + ky) * A_COLS + tx + kx) * A_PITCH];
            const float* wb = &ws[kk * 64 * 27];
#pragma unroll 2
            for (int c = 0; c < 64; c++) {
                float x0 = p0[c], x1 = p1[c];
                const float* wv = wb + c * 27;
#pragma unroll
                for (int j = 0; j < 27; j++) {
                    float w = wv[j];
                    acc0[j] += x0 * w;
                    acc1[j] += x1 * w;
                }
            }
        }
    }

    int wo = w0 + tx;
    if (wo < W_OUT) {
        int ho0 = h0 + ty, ho1 = h0 + ty + 8;
        if (ho0 < H_OUT) {
#pragma unroll
            for (int j = 0; j < 27; j++) {
                float v = acc0[j] + b_off[j];
                if (j >= 18) v = 1.f / (1.f + expf(-v));
                g_off[((size_t)(b * 27 + j) * H_OUT + ho0) * W_OUT + wo] = v;
            }
        }
        if (ho1 < H_OUT) {
#pragma unroll
            for (int j = 0; j < 27; j++) {
                float v = acc1[j] + b_off[j];
                if (j >= 18) v = 1.f / (1.f + expf(-v));
                g_off[((size_t)(b * 27 + j) * H_OUT + ho1) * W_OUT + wo] = v;
            }
        }
    }
}

// ---------------- fused deform-sample + GEMM + bias + ReLU ----------------
// Block: 256 threads. Tile: one output row (128 px, 126 valid) x 64 out channels.
// Taps streamed one at a time. S is transposed (ck-major, pixel-contiguous) with a
// rotation swizzle: element (c, p) lives at S[c*128 + ((p + 4*(c>>2)) & 127)].
//   - GEMM reads (all lanes same c, p0 = lane*4): conflict-free 512B row sweep.
//   - sampling stores (16 lanes same p-pair, c = 4*cg): 2-way conflicts only.
// Thread tile: 4 pixels x 8 outputs = 32 accumulators; W reads are warp-broadcast.
#define SMEM_B ((64 * 128 + 64 * 64 + 128 * 5) * 4)   // 51712 bytes

__global__ __launch_bounds__(256, 3) void k_deform_gemm(const float* __restrict__ bias,
                                                        float* __restrict__ out) {
    extern __shared__ float sm[];
    float* S   = sm;                 // [64][128] swizzled
    float* Wc  = sm + 64 * 128;      // [64][64] weight chunk for current tap
    float* twy = Wc + 64 * 64;       // [128] per-pixel tap params
    float* twx = twy + 128;
    float* tm  = twx + 128;
    int*   ty0 = (int*)(tm + 128);
    int*   tx0 = ty0 + 128;

    int b  = blockIdx.z;
    int ho = blockIdx.y;
    int t  = threadIdx.x;

    const float* xb = g_xnhwc + (size_t)b * HWIN * C_IN;

    // GEMM thread mapping: lanes sweep pixels, warps own contiguous output groups
    int p0  = (t & 31) * 4;          // pixel base (4 consecutive pixels)
    int og8 = (t >> 5) * 8;          // output base (8 consecutive outputs, same per warp)

    float acc[8][4];                 // [output][pixel]
#pragma unroll
    for (int j = 0; j < 8; j++)
#pragma unroll
        for (int i = 0; i < 4; i++) acc[j][i] = 0.f;

    for (int k = 0; k < 9; k++) {
        __syncthreads();             // S + params free (previous GEMM done)

        // ---- tap params: thread t < 128 handles pixel t ----
        if (t < 128) {
            int wo = min(t, W_OUT - 1);
            size_t base = ((size_t)(b * 27) * H_OUT + ho) * W_OUT + wo;
            // interleaved layout: off_y[k] = ch 2k, off_x[k] = ch 2k+1, mask = ch 18+k
            float oy = g_off[base + (size_t)(2 * k)     * HWOUT];
            float ox = g_off[base + (size_t)(2 * k + 1) * HWOUT];
            float m  = g_off[base + (size_t)(18 + k)    * HWOUT];
            int kh = k / 3, kw = k - kh * 3;
            float ys = (float)(ho + kh) + oy;
            float xs = (float)(wo + kw) + ox;
            float yf = floorf(ys), xf = floorf(xs);
            twy[t] = ys - yf; twx[t] = xs - xf; tm[t] = m;
            ty0[t] = (int)yf; tx0[t] = (int)xf;
        }
        // ---- W chunk for this tap (independent of S/params) ----
        for (int i = t; i < 64 * 64; i += 256) Wc[i] = g_wT[k * 64 * 64 + i];
        __syncthreads();

        // ---- bilinear sampling: lane = (pixel_pair<<4)|cg -> 256B-contiguous gathers ----
#pragma unroll
        for (int it = 0; it < 8; it++) {
            int j  = t + it * 256;
            int cg = j & 15;             // channel group (cq = cg*4)
            int p  = j >> 4;             // pixel 0..127
            int cq = cg << 2;
            int y0 = ty0[p], x0 = tx0[p];
            float wy = twy[p], wx = twx[p], m = tm[p];
            float w00 = (1.f - wy) * (1.f - wx) * m;
            float w01 = (1.f - wy) * wx * m;
            float w10 = wy * (1.f - wx) * m;
            float w11 = wy * wx * m;
            int y1 = y0 + 1, x1 = x0 + 1;
            float4 r = make_float4(0.f, 0.f, 0.f, 0.f);
            if ((unsigned)y0 < (unsigned)H_IN) {
                const float* row = xb + ((size_t)y0 * W_IN) * C_IN + cq;
                if ((unsigned)x0 < (unsigned)W_IN) {
                    float4 v = *(const float4*)(row + x0 * C_IN);
                    r.x += w00 * v.x; r.y += w00 * v.y; r.z += w00 * v.z; r.w += w00 * v.w;
                }
                if ((unsigned)x1 < (unsigned)W_IN) {
                    float4 v = *(const float4*)(row + x1 * C_IN);
                    r.x += w01 * v.x; r.y += w01 * v.y; r.z += w01 * v.z; r.w += w01 * v.w;
                }
            }
            if ((unsigned)y1 < (unsigned)H_IN) {
                const float* row = xb + ((size_t)y1 * W_IN) * C_IN + cq;
                if ((unsigned)x0 < (unsigned)W_IN) {
                    float4 v = *(const float4*)(row + x0 * C_IN);
                    r.x += w10 * v.x; r.y += w10 * v.y; r.z += w10 * v.z; r.w += w10 * v.w;
                }
                if ((unsigned)x1 < (unsigned)W_IN) {
                    float4 v = *(const float4*)(row + x1 * C_IN);
                    r.x += w11 * v.x; r.y += w11 * v.y; r.z += w11 * v.z; r.w += w11 * v.w;
                }
            }
            // transposed store with rotation swizzle: col = (p + 4*cg) & 127, rows cq..cq+3
            int col = (p + (cg << 2)) & 127;
            S[(cq + 0) * 128 + col] = r.x;
            S[(cq + 1) * 128 + col] = r.y;
            S[(cq + 2) * 128 + col] = r.z;
            S[(cq + 3) * 128 + col] = r.w;
        }
        __syncthreads();

        // ---- GEMM accumulate: 64 ck, 4 px x 8 out per thread ----
#pragma unroll
        for (int c4 = 0; c4 < 16; c4++) {
            int col = (p0 + (c4 << 2)) & 127;   // rotation for rows 4*c4 .. 4*c4+3
#pragma unroll
            for (int u = 0; u < 4; u++) {
                int c = (c4 << 2) + u;
                float4 s  = *(const float4*)&S[c * 128 + col];
                float4 wa = *(const float4*)&Wc[c * 64 + og8];
                float4 wb = *(const float4*)&Wc[c * 64 + og8 + 4];
                acc[0][0] += wa.x * s.x; acc[0][1] += wa.x * s.y; acc[0][2] += wa.x * s.z; acc[0][3] += wa.x * s.w;
                acc[1][0] += wa.y * s.x; acc[1][1] += wa.y * s.y; acc[1][2] += wa.y * s.z; acc[1][3] += wa.y * s.w;
                acc[2][0] += wa.z * s.x; acc[2][1] += wa.z * s.y; acc[2][2] += wa.z * s.z; acc[2][3] += wa.z * s.w;
                acc[3][0] += wa.w * s.x; acc[3][1] += wa.w * s.y; acc[3][2] += wa.w * s.z; acc[3][3] += wa.w * s.w;
                acc[4][0] += wb.x * s.x; acc[4][1] += wb.x * s.y; acc[4][2] += wb.x * s.z; acc[4][3] += wb.x * s.w;
                acc[5][0] += wb.y * s.x; acc[5][1] += wb.y * s.y; acc[5][2] += wb.y * s.z; acc[5][3] += wb.y * s.w;
                acc[6][0] += wb.z * s.x; acc[6][1] += wb.z * s.y; acc[6][2] += wb.z * s.z; acc[6][3] += wb.z * s.w;
                acc[7][0] += wb.w * s.x; acc[7][1] += wb.w * s.y; acc[7][2] += wb.w * s.z; acc[7][3] += wb.w * s.w;
            }
        }
    }

    // ---- epilogue: stage [o][p] in smem (reuse S), coalesced stores + bias + ReLU ----
    __syncthreads();
#pragma unroll
    for (int j = 0; j < 8; j++)
        *(float4*)&S[(og8 + j) * 128 + p0] =
            make_float4(acc[j][0], acc[j][1], acc[j][2], acc[j][3]);
    __syncthreads();
    for (int i = t; i < 64 * 128; i += 256) {
        int o = i >> 7, pp = i & 127;
        if (pp < W_OUT) {
            float v = S[i] + bias[o];
            out[(((size_t)b * C_OUT + o) * H_OUT + ho) * W_OUT + pp] = fmaxf(v, 0.f);
        }
    }
}

// ---------------- launch ----------------
extern "C" void kernel_launch(void* const* d_in, const int* in_sizes, int n_in,
                              void* d_out, int out_size) {
    const float* x      = (const float*)d_in[0];
    const float* w_off  = (const float*)d_in[1];
    const float* b_off  = (const float*)d_in[2];
    const float* weight = (const float*)d_in[3];
    const float* bias   = (const float*)d_in[4];
    float* out = (float*)d_out;
    (void)in_sizes; (void)n_in; (void)out_size;

    cudaFuncSetAttribute(k_offset_conv, cudaFuncAttributeMaxDynamicSharedMemorySize, SMEM_A);
    cudaFuncSetAttribute(k_deform_gemm, cudaFuncAttributeMaxDynamicSharedMemorySize, SMEM_B);

    k_transpose_x<<<dim3(HWIN / 32, C_IN / 32, B_N), dim3(32, 8)>>>(x);
    k_prep_w<<<(CK * C_OUT + 255) / 256, 256>>>(w_off, weight);
    k_offset_conv<<<dim3(4, 8, B_N), 256, SMEM_A>>>(b_off);
    k_deform_gemm<<<dim3(1, H_OUT, B_N), 256, SMEM_B>>>(bias, out);
}

// round 5
// speedup vs baseline: 2.7745x; 1.1508x over previous
#include <cuda_runtime.h>
#include <math.h>

#define B_N   4
#define C_IN  64
#define C_OUT 64
#define H_IN  128
#define W_IN  128
#define H_OUT 126
#define W_OUT 126
#define CK    576            // 9 * 64
#define HWIN  (H_IN * W_IN)
#define HWOUT (H_OUT * W_OUT)

// ---------------- scratch (device globals; no allocations allowed) ----------------
__device__ __align__(16) float g_xnhwc[B_N * HWIN * C_IN];        // 16 MB
__device__ __align__(16) float g_off[B_N * 27 * HWOUT];           // ~6.9 MB
__device__ __align__(16) float g_wT[CK * C_OUT];                  // [k*64+c][o]
__device__ __align__(16) float g_wOffT[CK * 28];                  // [k*64+c][28] (27 padded)

// ---------------- prep: NCHW -> NHWC transpose ----------------
__global__ void k_transpose_x(const float* __restrict__ x) {
    __shared__ float tile[32][33];
    int b   = blockIdx.z;
    int hw0 = blockIdx.x * 32;
    int c0  = blockIdx.y * 32;
    int tx = threadIdx.x, ty = threadIdx.y;
#pragma unroll
    for (int i = ty; i < 32; i += 8)
        tile[i][tx] = x[((size_t)(b * C_IN + c0 + i)) * HWIN + hw0 + tx];
    __syncthreads();
#pragma unroll
    for (int i = ty; i < 32; i += 8)
        g_xnhwc[((size_t)b * HWIN + hw0 + i) * C_IN + c0 + tx] = tile[tx][i];
}

// ---------------- prep: weight transposes to ck-major (ck = k*64 + c) ----------------
__global__ void k_prep_w(const float* __restrict__ w_off, const float* __restrict__ weight) {
    int t = blockIdx.x * blockDim.x + threadIdx.x;
    if (t < CK * 28) {
        int ck = t / 28, co = t - ck * 28;
        int kk = ck >> 6, cc = ck & 63;
        g_wOffT[t] = (co < 27) ? w_off[co * CK + cc * 9 + kk] : 0.f;
    }
    if (t < CK * C_OUT) {
        int ck = t >> 6, o = t & 63;
        int kk = ck >> 6, cc = ck & 63;
        g_wT[t] = weight[o * CK + cc * 9 + kk];
    }
}

// ---------------- offset conv: x (NHWC) * w_off -> g_off (sigmoid on ch 18..26) ----------------
#define A_PITCH 65
#define A_ROWS  18
#define A_COLS  34
#define A_NPIX  (A_ROWS * A_COLS)          // 612
#define SMEM_A  ((A_NPIX * A_PITCH + CK * 28) * 4)   // 223632 bytes

__global__ __launch_bounds__(256, 1) void k_offset_conv(const float* __restrict__ b_off) {
    extern __shared__ float sm[];
    float* patch = sm;                       // [612][65]
    float* ws    = sm + A_NPIX * A_PITCH;    // [576][28], float4-aligned rows

    int b  = blockIdx.z;
    int h0 = blockIdx.y * 16;
    int w0 = blockIdx.x * 32;
    int t  = threadIdx.x;

    for (int i = t; i < CK * 28; i += 256) ws[i] = g_wOffT[i];

    const float* xb = g_xnhwc + (size_t)b * HWIN * C_IN;
    for (int i = t; i < A_NPIX * C_IN; i += 256) {
        int c = i & 63, pix = i >> 6;
        int r = pix / A_COLS, col = pix - r * A_COLS;
        int hh = min(h0 + r,   H_IN - 1);
        int ww = min(w0 + col, W_IN - 1);
        patch[pix * A_PITCH + c] = xb[(hh * W_IN + ww) * C_IN + c];
    }
    __syncthreads();

    int tx = t & 31, ty = t >> 5;            // 8 rows x 32 cols, 2 pixels/thread
    float acc0[28], acc1[28];
#pragma unroll
    for (int j = 0; j < 28; j++) { acc0[j] = 0.f; acc1[j] = 0.f; }

#pragma unroll
    for (int ky = 0; ky < 3; ky++) {
#pragma unroll
        for (int kx = 0; kx < 3; kx++) {
            int kk = ky * 3 + kx;
            const float* p0 = &patch[((ty + ky)     * A_COLS + tx + kx) * A_PITCH];
            const float* p1 = &patch[((ty + 8 + ky) * A_COLS + tx + kx) * A_PITCH];
            const float4* wb = (const float4*)&ws[kk * 64 * 28];
#pragma unroll 2
            for (int c = 0; c < 64; c++) {
                float x0 = p0[c], x1 = p1[c];
                const float4* wv = wb + c * 7;
#pragma unroll
                for (int g = 0; g < 7; g++) {
                    float4 w4 = wv[g];
                    acc0[g*4+0] += x0 * w4.x; acc1[g*4+0] += x1 * w4.x;
                    acc0[g*4+1] += x0 * w4.y; acc1[g*4+1] += x1 * w4.y;
                    acc0[g*4+2] += x0 * w4.z; acc1[g*4+2] += x1 * w4.z;
                    acc0[g*4+3] += x0 * w4.w; acc1[g*4+3] += x1 * w4.w;
                }
            }
        }
    }

    int wo = w0 + tx;
    if (wo < W_OUT) {
        int ho0 = h0 + ty, ho1 = h0 + ty + 8;
        if (ho0 < H_OUT) {
#pragma unroll
            for (int j = 0; j < 27; j++) {
                float v = acc0[j] + b_off[j];
                if (j >= 18) v = 1.f / (1.f + expf(-v));
                g_off[((b * 27 + j) * H_OUT + ho0) * W_OUT + wo] = v;
            }
        }
        if (ho1 < H_OUT) {
#pragma unroll
            for (int j = 0; j < 27; j++) {
                float v = acc1[j] + b_off[j];
                if (j >= 18) v = 1.f / (1.f + expf(-v));
                g_off[((b * 27 + j) * H_OUT + ho1) * W_OUT + wo] = v;
            }
        }
    }
}

// ---------------- fused deform-sample + GEMM + bias + ReLU ----------------
// Block: 256 threads. Tile: one output row (128 px, 126 valid) x 64 out channels.
// Taps streamed one at a time. S is transposed (ck-major, pixel-contiguous) with a
// rotation swizzle: element (c, p) lives at S[c*128 + ((p + 4*(c>>2)) & 127)].
// Thread tile: 4 pixels x 8 outputs = 32 accumulators; W reads are warp-broadcast.
#define SMEM_B ((64 * 128 + 64 * 64 + 128 * 5) * 4)   // 51712 bytes -> 4 blocks/SM

__global__ __launch_bounds__(256, 4) void k_deform_gemm(const float* __restrict__ bias,
                                                        float* __restrict__ out) {
    extern __shared__ float sm[];
    float* S   = sm;                 // [64][128] swizzled
    float* Wc  = sm + 64 * 128;      // [64][64] weight chunk for current tap
    float* twy = Wc + 64 * 64;       // [128] per-pixel tap params
    float* twx = twy + 128;
    float* tm  = twx + 128;
    int*   ty0 = (int*)(tm + 128);
    int*   tx0 = ty0 + 128;

    int b  = blockIdx.z;
    int ho = blockIdx.y;
    int t  = threadIdx.x;

    const float* xb = g_xnhwc + b * (HWIN * C_IN);   // 4M floats per batch: int-safe per-batch base

    // GEMM thread mapping: lanes sweep pixels, warps own contiguous output groups
    int p0  = (t & 31) * 4;          // pixel base (4 consecutive pixels)
    int og8 = (t >> 5) * 8;          // output base (8 consecutive outputs, same per warp)

    float acc[8][4];                 // [output][pixel]
#pragma unroll
    for (int j = 0; j < 8; j++)
#pragma unroll
        for (int i = 0; i < 4; i++) acc[j][i] = 0.f;

    for (int k = 0; k < 9; k++) {
        __syncthreads();             // S + params free (previous GEMM done)

        // ---- tap params: thread t < 128 handles pixel t ----
        if (t < 128) {
            int wo = min(t, W_OUT - 1);
            int base = ((b * 27) * H_OUT + ho) * W_OUT + wo;
            // interleaved layout: off_y[k] = ch 2k, off_x[k] = ch 2k+1, mask = ch 18+k
            float oy = g_off[base + (2 * k)     * HWOUT];
            float ox = g_off[base + (2 * k + 1) * HWOUT];
            float m  = g_off[base + (18 + k)    * HWOUT];
            int kh = k / 3, kw = k - kh * 3;
            float ys = (float)(ho + kh) + oy;
            float xs = (float)(wo + kw) + ox;
            float yf = floorf(ys), xf = floorf(xs);
            twy[t] = ys - yf; twx[t] = xs - xf; tm[t] = m;
            ty0[t] = (int)yf; tx0[t] = (int)xf;
        }
        // ---- W chunk for this tap (independent of S/params) ----
        for (int i = t; i < 64 * 64; i += 256) Wc[i] = g_wT[k * 64 * 64 + i];
        __syncthreads();

        // ---- bilinear sampling: lane = (pixel_pair<<4)|cg -> 256B-contiguous gathers ----
#pragma unroll
        for (int it = 0; it < 8; it++) {
            int j  = t + it * 256;
            int cg = j & 15;             // channel group (cq = cg*4)
            int p  = j >> 4;             // pixel 0..127
            int cq = cg << 2;
            int y0 = ty0[p], x0 = tx0[p];
            float wy = twy[p], wx = twx[p], m = tm[p];
            float w00 = (1.f - wy) * (1.f - wx) * m;
            float w01 = (1.f - wy) * wx * m;
            float w10 = wy * (1.f - wx) * m;
            float w11 = wy * wx * m;
            int y1 = y0 + 1, x1 = x0 + 1;
            float4 r = make_float4(0.f, 0.f, 0.f, 0.f);
            if ((unsigned)y0 < (unsigned)H_IN) {
                const float* row = xb + (y0 * W_IN) * C_IN + cq;
                if ((unsigned)x0 < (unsigned)W_IN) {
                    float4 v = *(const float4*)(row + x0 * C_IN);
                    r.x += w00 * v.x; r.y += w00 * v.y; r.z += w00 * v.z; r.w += w00 * v.w;
                }
                if ((unsigned)x1 < (unsigned)W_IN) {
                    float4 v = *(const float4*)(row + x1 * C_IN);
                    r.x += w01 * v.x; r.y += w01 * v.y; r.z += w01 * v.z; r.w += w01 * v.w;
                }
            }
            if ((unsigned)y1 < (unsigned)H_IN) {
                const float* row = xb + (y1 * W_IN) * C_IN + cq;
                if ((unsigned)x0 < (unsigned)W_IN) {
                    float4 v = *(const float4*)(row + x0 * C_IN);
                    r.x += w10 * v.x; r.y += w10 * v.y; r.z += w10 * v.z; r.w += w10 * v.w;
                }
                if ((unsigned)x1 < (unsigned)W_IN) {
                    float4 v = *(const float4*)(row + x1 * C_IN);
                    r.x += w11 * v.x; r.y += w11 * v.y; r.z += w11 * v.z; r.w += w11 * v.w;
                }
            }
            // transposed store with rotation swizzle: col = (p + 4*cg) & 127, rows cq..cq+3
            int col = (p + (cg << 2)) & 127;
            S[(cq + 0) * 128 + col] = r.x;
            S[(cq + 1) * 128 + col] = r.y;
            S[(cq + 2) * 128 + col] = r.z;
            S[(cq + 3) * 128 + col] = r.w;
        }
        __syncthreads();

        // ---- GEMM accumulate: 64 ck, 4 px x 8 out per thread ----
#pragma unroll
        for (int c4 = 0; c4 < 16; c4++) {
            int col = (p0 + (c4 << 2)) & 127;   // rotation for rows 4*c4 .. 4*c4+3
#pragma unroll
            for (int u = 0; u < 4; u++) {
                int c = (c4 << 2) + u;
                float4 s  = *(const float4*)&S[c * 128 + col];
                float4 wa = *(const float4*)&Wc[c * 64 + og8];
                float4 wb = *(const float4*)&Wc[c * 64 + og8 + 4];
                acc[0][0] += wa.x * s.x; acc[0][1] += wa.x * s.y; acc[0][2] += wa.x * s.z; acc[0][3] += wa.x * s.w;
                acc[1][0] += wa.y * s.x; acc[1][1] += wa.y * s.y; acc[1][2] += wa.y * s.z; acc[1][3] += wa.y * s.w;
                acc[2][0] += wa.z * s.x; acc[2][1] += wa.z * s.y; acc[2][2] += wa.z * s.z; acc[2][3] += wa.z * s.w;
                acc[3][0] += wa.w * s.x; acc[3][1] += wa.w * s.y; acc[3][2] += wa.w * s.z; acc[3][3] += wa.w * s.w;
                acc[4][0] += wb.x * s.x; acc[4][1] += wb.x * s.y; acc[4][2] += wb.x * s.z; acc[4][3] += wb.x * s.w;
                acc[5][0] += wb.y * s.x; acc[5][1] += wb.y * s.y; acc[5][2] += wb.y * s.z; acc[5][3] += wb.y * s.w;
                acc[6][0] += wb.z * s.x; acc[6][1] += wb.z * s.y; acc[6][2] += wb.z * s.z; acc[6][3] += wb.z * s.w;
                acc[7][0] += wb.w * s.x; acc[7][1] += wb.w * s.y; acc[7][2] += wb.w * s.z; acc[7][3] += wb.w * s.w;
            }
        }
    }

    // ---- epilogue: stage [o][p] in smem (reuse S), coalesced stores + bias + ReLU ----
    __syncthreads();
#pragma unroll
    for (int j = 0; j < 8; j++)
        *(float4*)&S[(og8 + j) * 128 + p0] =
            make_float4(acc[j][0], acc[j][1], acc[j][2], acc[j][3]);
    __syncthreads();
    for (int i = t; i < 64 * 128; i += 256) {
        int o = i >> 7, pp = i & 127;
        if (pp < W_OUT) {
            float v = S[i] + bias[o];
            out[((b * C_OUT + o) * H_OUT + ho) * W_OUT + pp] = fmaxf(v, 0.f);
        }
    }
}

// ---------------- launch ----------------
extern "C" void kernel_launch(void* const* d_in, const int* in_sizes, int n_in,
                              void* d_out, int out_size) {
    const float* x      = (const float*)d_in[0];
    const float* w_off  = (const float*)d_in[1];
    const float* b_off  = (const float*)d_in[2];
    const float* weight = (const float*)d_in[3];
    const float* bias   = (const float*)d_in[4];
    float* out = (float*)d_out;
    (void)in_sizes; (void)n_in; (void)out_size;

    cudaFuncSetAttribute(k_offset_conv, cudaFuncAttributeMaxDynamicSharedMemorySize, SMEM_A);
    cudaFuncSetAttribute(k_deform_gemm, cudaFuncAttributeMaxDynamicSharedMemorySize, SMEM_B);

    k_transpose_x<<<dim3(HWIN / 32, C_IN / 32, B_N), dim3(32, 8)>>>(x);
    k_prep_w<<<(CK * C_OUT + 255) / 256, 256>>>(w_off, weight);
    k_offset_conv<<<dim3(4, 8, B_N), 256, SMEM_A>>>(b_off);
    k_deform_gemm<<<dim3(1, H_OUT, B_N), 256, SMEM_B>>>(bias, out);
}

// round 6
// speedup vs baseline: 2.9552x; 1.0651x over previous
#include <cuda_runtime.h>
#include <math.h>
#include <stdint.h>

#define B_N   4
#define C_IN  64
#define C_OUT 64
#define H_IN  128
#define W_IN  128
#define H_OUT 126
#define W_OUT 126
#define CK    576            // 9 * 64
#define HWIN  (H_IN * W_IN)
#define HWOUT (H_OUT * W_OUT)

// ---------------- scratch (device globals; no allocations allowed) ----------------
__device__ __align__(16) float g_xnhwc[B_N * HWIN * C_IN];        // 16 MB
__device__ __align__(16) float g_off[B_N * 27 * HWOUT];           // ~6.9 MB
__device__ __align__(16) float g_wfrag[9 * 8 * 8 * 32 * 2];       // B-fragment packed main weights (144 KB)
__device__ __align__(16) float g_wOffT[CK * 28];                  // [k*64+c][28] (27 padded)

// ---------------- prep: NCHW -> NHWC transpose ----------------
__global__ void k_transpose_x(const float* __restrict__ x) {
    __shared__ float tile[32][33];
    int b   = blockIdx.z;
    int hw0 = blockIdx.x * 32;
    int c0  = blockIdx.y * 32;
    int tx = threadIdx.x, ty = threadIdx.y;
#pragma unroll
    for (int i = ty; i < 32; i += 8)
        tile[i][tx] = x[((size_t)(b * C_IN + c0 + i)) * HWIN + hw0 + tx];
    __syncthreads();
#pragma unroll
    for (int i = ty; i < 32; i += 8)
        g_xnhwc[((size_t)b * HWIN + hw0 + i) * C_IN + c0 + tx] = tile[tx][i];
}

// ---------------- prep: offset-conv weight transpose + main-weight B-fragment pack ----------------
// B fragment (mma.m16n8k8.row.col): b0 = B[k=lane&3][n=lane>>2], b1 = B[k=(lane&3)+4][n=lane>>2]
// g_wfrag[((k*8 + s)*8 + nt)*64 + lane*2 + e] = weight[o=nt*8+(lane>>2)][c = s*8 + (lane&3) + 4e][tap k]
__global__ void k_prep_w(const float* __restrict__ w_off, const float* __restrict__ weight) {
    int t = blockIdx.x * blockDim.x + threadIdx.x;
    if (t < CK * 28) {
        int ck = t / 28, co = t - ck * 28;
        int kk = ck >> 6, cc = ck & 63;
        g_wOffT[t] = (co < 27) ? w_off[co * CK + cc * 9 + kk] : 0.f;
    }
    if (t < 9 * 8 * 8 * 32 * 2) {
        int e    = t & 1;
        int lane = (t >> 1) & 31;
        int nt   = (t >> 6) & 7;
        int s    = (t >> 9) & 7;
        int k    = t >> 12;
        int o = nt * 8 + (lane >> 2);
        int c = s * 8 + (lane & 3) + 4 * e;
        g_wfrag[t] = weight[o * CK + c * 9 + k];
    }
}

// ---------------- offset conv: x (NHWC) * w_off -> g_off (sigmoid on ch 18..26) ----------------
#define A_PITCH 65
#define A_ROWS  18
#define A_COLS  34
#define A_NPIX  (A_ROWS * A_COLS)          // 612
#define SMEM_A  ((A_NPIX * A_PITCH + CK * 28) * 4)   // 223632 bytes

__global__ __launch_bounds__(256, 1) void k_offset_conv(const float* __restrict__ b_off) {
    extern __shared__ float sm[];
    float* patch = sm;                       // [612][65]
    float* ws    = sm + A_NPIX * A_PITCH;    // [576][28], float4-aligned rows

    int b  = blockIdx.z;
    int h0 = blockIdx.y * 16;
    int w0 = blockIdx.x * 32;
    int t  = threadIdx.x;

    for (int i = t; i < CK * 28; i += 256) ws[i] = g_wOffT[i];

    const float* xb = g_xnhwc + (size_t)b * HWIN * C_IN;
    for (int i = t; i < A_NPIX * C_IN; i += 256) {
        int c = i & 63, pix = i >> 6;
        int r = pix / A_COLS, col = pix - r * A_COLS;
        int hh = min(h0 + r,   H_IN - 1);
        int ww = min(w0 + col, W_IN - 1);
        patch[pix * A_PITCH + c] = xb[(hh * W_IN + ww) * C_IN + c];
    }
    __syncthreads();

    int tx = t & 31, ty = t >> 5;            // 8 rows x 32 cols, 2 pixels/thread
    float acc0[28], acc1[28];
#pragma unroll
    for (int j = 0; j < 28; j++) { acc0[j] = 0.f; acc1[j] = 0.f; }

#pragma unroll
    for (int ky = 0; ky < 3; ky++) {
#pragma unroll
        for (int kx = 0; kx < 3; kx++) {
            int kk = ky * 3 + kx;
            const float* p0 = &patch[((ty + ky)     * A_COLS + tx + kx) * A_PITCH];
            const float* p1 = &patch[((ty + 8 + ky) * A_COLS + tx + kx) * A_PITCH];
            const float4* wb = (const float4*)&ws[kk * 64 * 28];
#pragma unroll 2
            for (int c = 0; c < 64; c++) {
                float x0 = p0[c], x1 = p1[c];
                const float4* wv = wb + c * 7;
#pragma unroll
                for (int g = 0; g < 7; g++) {
                    float4 w4 = wv[g];
                    acc0[g*4+0] += x0 * w4.x; acc1[g*4+0] += x1 * w4.x;
                    acc0[g*4+1] += x0 * w4.y; acc1[g*4+1] += x1 * w4.y;
                    acc0[g*4+2] += x0 * w4.z; acc1[g*4+2] += x1 * w4.z;
                    acc0[g*4+3] += x0 * w4.w; acc1[g*4+3] += x1 * w4.w;
                }
            }
        }
    }

    int wo = w0 + tx;
    if (wo < W_OUT) {
        int ho0 = h0 + ty, ho1 = h0 + ty + 8;
        if (ho0 < H_OUT) {
#pragma unroll
            for (int j = 0; j < 27; j++) {
                float v = acc0[j] + b_off[j];
                if (j >= 18) v = 1.f / (1.f + expf(-v));
                g_off[((b * 27 + j) * H_OUT + ho0) * W_OUT + wo] = v;
            }
        }
        if (ho1 < H_OUT) {
#pragma unroll
            for (int j = 0; j < 27; j++) {
                float v = acc1[j] + b_off[j];
                if (j >= 18) v = 1.f / (1.f + expf(-v));
                g_off[((b * 27 + j) * H_OUT + ho1) * W_OUT + wo] = v;
            }
        }
    }
}

// ---------------- fused deform-sample + TF32 MMA GEMM + bias + ReLU ----------------
// Block: 256 threads (8 warps). Tile: one output row (128 px) x 64 out channels.
// Warp tile: 32 px x 32 out = 2x4 m16n8k8 mma tiles, K=64 per tap (8 ksteps).
// S stored in A-fragment order: float slot = ((wm*2+f)*8 + s)*128 + ((gid*4+t4)^s)*4 + reg
//   where p = wm*32 + f*16 + 8h + gid, c = s*8 + 4*half + t4, reg = h + 2*half.
// The XOR-by-s swizzle makes GEMM A-loads (LDS.128, lane^s) conflict-free while
// sampling stores stay 2-way.
#define SMEM_B ((8192 + 4096 + 640) * 4)   // S-frag 32KB + W-frag chunk 16KB + params

__device__ __forceinline__ void mma_tf32(float* d, const uint4 a, const uint2 b) {
    asm volatile(
        "mma.sync.aligned.m16n8k8.row.col.f32.tf32.tf32.f32 "
        "{%0,%1,%2,%3},{%4,%5,%6,%7},{%8,%9},{%0,%1,%2,%3};"
        : "+f"(d[0]), "+f"(d[1]), "+f"(d[2]), "+f"(d[3])
        : "r"(a.x), "r"(a.y), "r"(a.z), "r"(a.w), "r"(b.x), "r"(b.y));
}

__global__ __launch_bounds__(256, 3) void k_deform_gemm(const float* __restrict__ bias,
                                                        float* __restrict__ out) {
    extern __shared__ float sm[];
    float* S   = sm;                 // [8192] A-fragment layout
    float* Wc  = sm + 8192;          // [4096] B-fragment chunk for current tap
    float* twy = Wc + 4096;          // [128] per-pixel tap params
    float* twx = twy + 128;
    float* tm  = twx + 128;
    int*   ty0 = (int*)(tm + 128);
    int*   tx0 = ty0 + 128;

    int b  = blockIdx.z;
    int ho = blockIdx.y;
    int t  = threadIdx.x;

    const float* xb = g_xnhwc + b * (HWIN * C_IN);

    int lane = t & 31;
    int wrp  = t >> 5;
    int wm   = wrp & 3;              // M-tile: pixels [wm*32, wm*32+32)
    int wn   = wrp >> 2;             // N-tile: outputs [wn*32, wn*32+32)
    int t4   = lane & 3, gid = lane >> 2;

    float acc[2][4][4];              // [mt][nt4][reg]
#pragma unroll
    for (int i = 0; i < 2; i++)
#pragma unroll
        for (int j = 0; j < 4; j++)
#pragma unroll
            for (int r = 0; r < 4; r++) acc[i][j][r] = 0.f;

    for (int k = 0; k < 9; k++) {
        __syncthreads();             // S + Wc + params free (previous GEMM done)

        // ---- tap params: thread t < 128 handles pixel t ----
        if (t < 128) {
            int wo = min(t, W_OUT - 1);
            int base = ((b * 27) * H_OUT + ho) * W_OUT + wo;
            // interleaved layout: off_y[k] = ch 2k, off_x[k] = ch 2k+1, mask = ch 18+k
            float oy = g_off[base + (2 * k)     * HWOUT];
            float ox = g_off[base + (2 * k + 1) * HWOUT];
            float m  = g_off[base + (18 + k)    * HWOUT];
            int kh = k / 3, kw = k - kh * 3;
            float ys = (float)(ho + kh) + oy;
            float xs = (float)(wo + kw) + ox;
            float yf = floorf(ys), xf = floorf(xs);
            twy[t] = ys - yf; twx[t] = xs - xf; tm[t] = m;
            ty0[t] = (int)yf; tx0[t] = (int)xf;
        }
        // ---- W-fragment chunk for this tap ----
        {
            const float4* src = (const float4*)&g_wfrag[k * 4096];
            float4* dst = (float4*)Wc;
            for (int i = t; i < 1024; i += 256) dst[i] = src[i];
        }
        __syncthreads();

        // ---- bilinear sampling into A-fragment layout ----
#pragma unroll
        for (int it = 0; it < 8; it++) {
            int j  = t + it * 256;
            int cg = j & 15;             // channel group (cq = cg*4)
            int p  = j >> 4;             // pixel 0..127
            int cq = cg << 2;
            int y0 = ty0[p], x0 = tx0[p];
            float wy = twy[p], wx = twx[p], m = tm[p];
            float w00 = (1.f - wy) * (1.f - wx) * m;
            float w01 = (1.f - wy) * wx * m;
            float w10 = wy * (1.f - wx) * m;
            float w11 = wy * wx * m;
            int y1 = y0 + 1, x1 = x0 + 1;
            float rv[4] = {0.f, 0.f, 0.f, 0.f};
            if ((unsigned)y0 < (unsigned)H_IN) {
                const float* row = xb + (y0 * W_IN) * C_IN + cq;
                if ((unsigned)x0 < (unsigned)W_IN) {
                    float4 v = *(const float4*)(row + x0 * C_IN);
                    rv[0] += w00 * v.x; rv[1] += w00 * v.y; rv[2] += w00 * v.z; rv[3] += w00 * v.w;
                }
                if ((unsigned)x1 < (unsigned)W_IN) {
                    float4 v = *(const float4*)(row + x1 * C_IN);
                    rv[0] += w01 * v.x; rv[1] += w01 * v.y; rv[2] += w01 * v.z; rv[3] += w01 * v.w;
                }
            }
            if ((unsigned)y1 < (unsigned)H_IN) {
                const float* row = xb + (y1 * W_IN) * C_IN + cq;
                if ((unsigned)x0 < (unsigned)W_IN) {
                    float4 v = *(const float4*)(row + x0 * C_IN);
                    rv[0] += w10 * v.x; rv[1] += w10 * v.y; rv[2] += w10 * v.z; rv[3] += w10 * v.w;
                }
                if ((unsigned)x1 < (unsigned)W_IN) {
                    float4 v = *(const float4*)(row + x1 * C_IN);
                    rv[0] += w11 * v.x; rv[1] += w11 * v.y; rv[2] += w11 * v.z; rv[3] += w11 * v.w;
                }
            }
            // scatter into A-fragment slots
            int s    = cg >> 1;
            int reg  = ((p >> 3) & 1) + 2 * (cg & 1);       // h + 2*half
            int base = (((p >> 4) * 8) + s) * 128 + reg;    // (wm*2+f) = p>>4
            int gl4  = (p & 7) << 2;                        // gid*4
#pragma unroll
            for (int u = 0; u < 4; u++)
                S[base + (((gl4 | u) ^ s) << 2)] = rv[u];
        }
        __syncthreads();

        // ---- TF32 MMA: K=64 for this tap, 8 ksteps ----
#pragma unroll
        for (int s = 0; s < 8; s++) {
            int aoff = ((lane ^ s) << 2);
            uint4 A0 = *(const uint4*)&S[((wm * 2 + 0) * 8 + s) * 128 + aoff];
            uint4 A1 = *(const uint4*)&S[((wm * 2 + 1) * 8 + s) * 128 + aoff];
#pragma unroll
            for (int nt4 = 0; nt4 < 4; nt4++) {
                int nt = wn * 4 + nt4;
                uint2 Bv = *(const uint2*)&Wc[((s * 8 + nt) * 32 + lane) * 2];
                mma_tf32(acc[0][nt4], A0, Bv);
                mma_tf32(acc[1][nt4], A1, Bv);
            }
        }
    }

    // ---- epilogue: stage [o][p] in smem (pitch 132, conflict-free), coalesced stores ----
    __syncthreads();
    float* outS = sm;                // 64*132 = 8448 floats <= 12288 available
#pragma unroll
    for (int mt = 0; mt < 2; mt++) {
        int p0 = wm * 32 + mt * 16 + gid;
#pragma unroll
        for (int nt4 = 0; nt4 < 4; nt4++) {
            int n0 = (wn * 4 + nt4) * 8 + t4 * 2;
            outS[(n0 + 0) * 132 + p0]     = acc[mt][nt4][0];
            outS[(n0 + 1) * 132 + p0]     = acc[mt][nt4][1];
            outS[(n0 + 0) * 132 + p0 + 8] = acc[mt][nt4][2];
            outS[(n0 + 1) * 132 + p0 + 8] = acc[mt][nt4][3];
        }
    }
    __syncthreads();
    for (int i = t; i < 64 * 128; i += 256) {
        int o = i >> 7, pp = i & 127;
        if (pp < W_OUT) {
            float v = outS[o * 132 + pp] + bias[o];
            out[((b * C_OUT + o) * H_OUT + ho) * W_OUT + pp] = fmaxf(v, 0.f);
        }
    }
}

// ---------------- launch ----------------
extern "C" void kernel_launch(void* const* d_in, const int* in_sizes, int n_in,
                              void* d_out, int out_size) {
    const float* x      = (const float*)d_in[0];
    const float* w_off  = (const float*)d_in[1];
    const float* b_off  = (const float*)d_in[2];
    const float* weight = (const float*)d_in[3];
    const float* bias   = (const float*)d_in[4];
    float* out = (float*)d_out;
    (void)in_sizes; (void)n_in; (void)out_size;

    cudaFuncSetAttribute(k_offset_conv, cudaFuncAttributeMaxDynamicSharedMemorySize, SMEM_A);
    cudaFuncSetAttribute(k_deform_gemm, cudaFuncAttributeMaxDynamicSharedMemorySize, SMEM_B);

    k_transpose_x<<<dim3(HWIN / 32, C_IN / 32, B_N), dim3(32, 8)>>>(x);
    k_prep_w<<<(9 * 8 * 8 * 32 * 2 + 255) / 256, 256>>>(w_off, weight);
    k_offset_conv<<<dim3(4, 8, B_N), 256, SMEM_A>>>(b_off);
    k_deform_gemm<<<dim3(1, H_OUT, B_N), 256, SMEM_B>>>(bias, out);
}

// round 7
// speedup vs baseline: 3.0272x; 1.0244x over previous
#include <cuda_runtime.h>
#include <math.h>
#include <stdint.h>

#define B_N   4
#define C_IN  64
#define C_OUT 64
#define H_IN  128
#define W_IN  128
#define H_OUT 126
#define W_OUT 126
#define CK    576            // 9 * 64
#define HWIN  (H_IN * W_IN)
#define HWOUT (H_OUT * W_OUT)
#define NFRAG (9 * 8 * 8 * 32 * 2)   // 36864 fragment floats

// ---------------- scratch (device globals; no allocations allowed) ----------------
__device__ __align__(16) float g_xnhwc[B_N * HWIN * C_IN];        // 16 MB
__device__ __align__(16) float g_off[B_N * 27 * HWOUT];           // ~6.9 MB
__device__ __align__(16) float g_wfragH[NFRAG];                   // tf32-hi B fragments
__device__ __align__(16) float g_wfragL[NFRAG];                   // residual B fragments
__device__ __align__(16) float g_wOffT[CK * 28];                  // [k*64+c][28] (27 padded)

__device__ __forceinline__ float tf32_hi(float a) {
    return __uint_as_float(__float_as_uint(a) & 0xFFFFE000u);
}

// ---------------- prep: NCHW -> NHWC transpose ----------------
__global__ void k_transpose_x(const float* __restrict__ x) {
    __shared__ float tile[32][33];
    int b   = blockIdx.z;
    int hw0 = blockIdx.x * 32;
    int c0  = blockIdx.y * 32;
    int tx = threadIdx.x, ty = threadIdx.y;
#pragma unroll
    for (int i = ty; i < 32; i += 8)
        tile[i][tx] = x[((size_t)(b * C_IN + c0 + i)) * HWIN + hw0 + tx];
    __syncthreads();
#pragma unroll
    for (int i = ty; i < 32; i += 8)
        g_xnhwc[((size_t)b * HWIN + hw0 + i) * C_IN + c0 + tx] = tile[tx][i];
}

// ---------------- prep: offset-weight transpose + main-weight hi/lo B-fragment pack ----------------
// B fragment (mma.m16n8k8.row.col): element e of lane = B[k=(lane&3)+4e][n=lane>>2]
// g_wfrag*[((k*8 + s)*8 + nt)*64 + lane*2 + e] = weight[o=nt*8+(lane>>2)][c=s*8+(lane&3)+4e][tap k]
__global__ void k_prep_w(const float* __restrict__ w_off, const float* __restrict__ weight) {
    int t = blockIdx.x * blockDim.x + threadIdx.x;
    if (t < CK * 28) {
        int ck = t / 28, co = t - ck * 28;
        int kk = ck >> 6, cc = ck & 63;
        g_wOffT[t] = (co < 27) ? w_off[co * CK + cc * 9 + kk] : 0.f;
    }
    if (t < NFRAG) {
        int e    = t & 1;
        int lane = (t >> 1) & 31;
        int nt   = (t >> 6) & 7;
        int s    = (t >> 9) & 7;
        int k    = t >> 12;
        int o = nt * 8 + (lane >> 2);
        int c = s * 8 + (lane & 3) + 4 * e;
        float w  = weight[o * CK + c * 9 + k];
        float wh = tf32_hi(w);
        g_wfragH[t] = wh;
        g_wfragL[t] = w - wh;
    }
}

// ---------------- offset conv: x (NHWC) * w_off -> g_off (sigmoid on ch 18..26) ----------------
#define A_PITCH 65
#define A_ROWS  18
#define A_COLS  34
#define A_NPIX  (A_ROWS * A_COLS)          // 612
#define SMEM_A  ((A_NPIX * A_PITCH + CK * 28) * 4)   // 223632 bytes

__global__ __launch_bounds__(256, 1) void k_offset_conv(const float* __restrict__ b_off) {
    extern __shared__ float sm[];
    float* patch = sm;                       // [612][65]
    float* ws    = sm + A_NPIX * A_PITCH;    // [576][28], float4-aligned rows

    int b  = blockIdx.z;
    int h0 = blockIdx.y * 16;
    int w0 = blockIdx.x * 32;
    int t  = threadIdx.x;

    for (int i = t; i < CK * 28; i += 256) ws[i] = g_wOffT[i];

    const float* xb = g_xnhwc + (size_t)b * HWIN * C_IN;
    for (int i = t; i < A_NPIX * C_IN; i += 256) {
        int c = i & 63, pix = i >> 6;
        int r = pix / A_COLS, col = pix - r * A_COLS;
        int hh = min(h0 + r,   H_IN - 1);
        int ww = min(w0 + col, W_IN - 1);
        patch[pix * A_PITCH + c] = xb[(hh * W_IN + ww) * C_IN + c];
    }
    __syncthreads();

    int tx = t & 31, ty = t >> 5;            // 8 rows x 32 cols, 2 pixels/thread
    float acc0[28], acc1[28];
#pragma unroll
    for (int j = 0; j < 28; j++) { acc0[j] = 0.f; acc1[j] = 0.f; }

#pragma unroll
    for (int ky = 0; ky < 3; ky++) {
#pragma unroll
        for (int kx = 0; kx < 3; kx++) {
            int kk = ky * 3 + kx;
            const float* p0 = &patch[((ty + ky)     * A_COLS + tx + kx) * A_PITCH];
            const float* p1 = &patch[((ty + 8 + ky) * A_COLS + tx + kx) * A_PITCH];
            const float4* wb = (const float4*)&ws[kk * 64 * 28];
#pragma unroll 2
            for (int c = 0; c < 64; c++) {
                float x0 = p0[c], x1 = p1[c];
                const float4* wv = wb + c * 7;
#pragma unroll
                for (int g = 0; g < 7; g++) {
                    float4 w4 = wv[g];
                    acc0[g*4+0] += x0 * w4.x; acc1[g*4+0] += x1 * w4.x;
                    acc0[g*4+1] += x0 * w4.y; acc1[g*4+1] += x1 * w4.y;
                    acc0[g*4+2] += x0 * w4.z; acc1[g*4+2] += x1 * w4.z;
                    acc0[g*4+3] += x0 * w4.w; acc1[g*4+3] += x1 * w4.w;
                }
            }
        }
    }

    int wo = w0 + tx;
    if (wo < W_OUT) {
        int ho0 = h0 + ty, ho1 = h0 + ty + 8;
        if (ho0 < H_OUT) {
#pragma unroll
            for (int j = 0; j < 27; j++) {
                float v = acc0[j] + b_off[j];
                if (j >= 18) v = 1.f / (1.f + expf(-v));
                g_off[((b * 27 + j) * H_OUT + ho0) * W_OUT + wo] = v;
            }
        }
        if (ho1 < H_OUT) {
#pragma unroll
            for (int j = 0; j < 27; j++) {
                float v = acc1[j] + b_off[j];
                if (j >= 18) v = 1.f / (1.f + expf(-v));
                g_off[((b * 27 + j) * H_OUT + ho1) * W_OUT + wo] = v;
            }
        }
    }
}

// ---------------- fused deform-sample + 3xTF32 MMA GEMM + bias + ReLU ----------------
// Block: 256 threads (8 warps). Tile: one output row (128 px) x 64 out channels.
// Warp tile: 32 px x 32 out = 2x4 m16n8k8 mma tiles, K=64 per tap (8 ksteps).
// All 9 taps' params hoisted to one upfront phase; B fragments read straight from
// global (L2/L1-hot, shared by 4 warps per block and all 504 blocks).
// S in A-fragment order with XOR-by-kstep swizzle (GEMM loads conflict-free).
#define SMEM_B ((8192 + 5 * 1152) * 4)   // 55808 bytes

__device__ __forceinline__ void mma_tf32(float* d, const uint4 a, const uint2 b) {
    asm volatile(
        "mma.sync.aligned.m16n8k8.row.col.f32.tf32.tf32.f32 "
        "{%0,%1,%2,%3},{%4,%5,%6,%7},{%8,%9},{%0,%1,%2,%3};"
        : "+f"(d[0]), "+f"(d[1]), "+f"(d[2]), "+f"(d[3])
        : "r"(a.x), "r"(a.y), "r"(a.z), "r"(a.w), "r"(b.x), "r"(b.y));
}

__global__ __launch_bounds__(256, 3) void k_deform_gemm(const float* __restrict__ bias,
                                                        float* __restrict__ out) {
    extern __shared__ float sm[];
    float* S   = sm;                 // [8192] A-fragment layout
    float* twy = sm + 8192;          // [9][128] per-(tap,pixel) params
    float* twx = twy + 1152;
    float* tm  = twx + 1152;
    int*   ty0 = (int*)(tm + 1152);
    int*   tx0 = ty0 + 1152;

    int b  = blockIdx.z;
    int ho = blockIdx.y;
    int t  = threadIdx.x;

    const float* xb = g_xnhwc + b * (HWIN * C_IN);

    int lane = t & 31;
    int wrp  = t >> 5;
    int wm   = wrp & 3;              // M-tile: pixels [wm*32, wm*32+32)
    int wn   = wrp >> 2;             // N-tile: outputs [wn*32, wn*32+32)
    int t4   = lane & 3, gid = lane >> 2;

    // ---- upfront: tap params for ALL 9 taps (coalesced over pixels) ----
    {
        int obase = ((b * 27) * H_OUT + ho) * W_OUT;
#pragma unroll
        for (int j = t; j < 1152; j += 256) {
            int k = j >> 7, p = j & 127;
            int wo = min(p, W_OUT - 1);
            // interleaved layout: off_y[k] = ch 2k, off_x[k] = ch 2k+1, mask = ch 18+k
            float oy = g_off[obase + wo + (2 * k)     * HWOUT];
            float ox = g_off[obase + wo + (2 * k + 1) * HWOUT];
            float m  = g_off[obase + wo + (18 + k)    * HWOUT];
            int kh = k / 3, kw = k - kh * 3;
            float ys = (float)(ho + kh) + oy;
            float xs = (float)(wo + kw) + ox;
            float yf = floorf(ys), xf = floorf(xs);
            twy[j] = ys - yf; twx[j] = xs - xf; tm[j] = m;
            ty0[j] = (int)yf; tx0[j] = (int)xf;
        }
    }

    float acc[2][4][4];              // [mt][nt4][reg]
#pragma unroll
    for (int i = 0; i < 2; i++)
#pragma unroll
        for (int j = 0; j < 4; j++)
#pragma unroll
            for (int r = 0; r < 4; r++) acc[i][j][r] = 0.f;

    for (int k = 0; k < 9; k++) {
        __syncthreads();             // params ready (k=0) / S free after prev MMA (k>0)

        // ---- bilinear sampling into A-fragment layout ----
#pragma unroll
        for (int it = 0; it < 8; it++) {
            int j  = t + it * 256;
            int cg = j & 15;             // channel group (cq = cg*4)
            int p  = j >> 4;             // pixel 0..127
            int kp = k * 128 + p;
            int cq = cg << 2;
            int y0 = ty0[kp], x0 = tx0[kp];
            float wy = twy[kp], wx = twx[kp], m = tm[kp];
            float w00 = (1.f - wy) * (1.f - wx) * m;
            float w01 = (1.f - wy) * wx * m;
            float w10 = wy * (1.f - wx) * m;
            float w11 = wy * wx * m;
            int y1 = y0 + 1, x1 = x0 + 1;
            float rv[4] = {0.f, 0.f, 0.f, 0.f};
            if ((unsigned)y0 < (unsigned)H_IN) {
                const float* row = xb + (y0 * W_IN) * C_IN + cq;
                if ((unsigned)x0 < (unsigned)W_IN) {
                    float4 v = *(const float4*)(row + x0 * C_IN);
                    rv[0] += w00 * v.x; rv[1] += w00 * v.y; rv[2] += w00 * v.z; rv[3] += w00 * v.w;
                }
                if ((unsigned)x1 < (unsigned)W_IN) {
                    float4 v = *(const float4*)(row + x1 * C_IN);
                    rv[0] += w01 * v.x; rv[1] += w01 * v.y; rv[2] += w01 * v.z; rv[3] += w01 * v.w;
                }
            }
            if ((unsigned)y1 < (unsigned)H_IN) {
                const float* row = xb + (y1 * W_IN) * C_IN + cq;
                if ((unsigned)x0 < (unsigned)W_IN) {
                    float4 v = *(const float4*)(row + x0 * C_IN);
                    rv[0] += w10 * v.x; rv[1] += w10 * v.y; rv[2] += w10 * v.z; rv[3] += w10 * v.w;
                }
                if ((unsigned)x1 < (unsigned)W_IN) {
                    float4 v = *(const float4*)(row + x1 * C_IN);
                    rv[0] += w11 * v.x; rv[1] += w11 * v.y; rv[2] += w11 * v.z; rv[3] += w11 * v.w;
                }
            }
            // scatter into A-fragment slots (XOR-by-s swizzle)
            int s    = cg >> 1;
            int reg  = ((p >> 3) & 1) + 2 * (cg & 1);       // h + 2*half
            int base = (((p >> 4) * 8) + s) * 128 + reg;    // (wm*2+f) = p>>4
            int gl4  = (p & 7) << 2;                        // gid*4
#pragma unroll
            for (int u = 0; u < 4; u++)
                S[base + (((gl4 | u) ^ s) << 2)] = rv[u];
        }
        __syncthreads();

        // ---- 3xTF32 MMA: K=64 for this tap, 8 ksteps ----
#pragma unroll
        for (int s = 0; s < 8; s++) {
            int aoff = ((lane ^ s) << 2);
            const float* A0p = &S[((wm * 2 + 0) * 8 + s) * 128 + aoff];
            const float* A1p = &S[((wm * 2 + 1) * 8 + s) * 128 + aoff];
            float4 A0f = *(const float4*)A0p;
            float4 A1f = *(const float4*)A1p;
            float4 A0hf, A0lf, A1hf, A1lf;
            A0hf.x = tf32_hi(A0f.x); A0lf.x = A0f.x - A0hf.x;
            A0hf.y = tf32_hi(A0f.y); A0lf.y = A0f.y - A0hf.y;
            A0hf.z = tf32_hi(A0f.z); A0lf.z = A0f.z - A0hf.z;
            A0hf.w = tf32_hi(A0f.w); A0lf.w = A0f.w - A0hf.w;
            A1hf.x = tf32_hi(A1f.x); A1lf.x = A1f.x - A1hf.x;
            A1hf.y = tf32_hi(A1f.y); A1lf.y = A1f.y - A1hf.y;
            A1hf.z = tf32_hi(A1f.z); A1lf.z = A1f.z - A1hf.z;
            A1hf.w = tf32_hi(A1f.w); A1lf.w = A1f.w - A1hf.w;
            uint4 A0h = *(uint4*)&A0hf, A0l = *(uint4*)&A0lf;
            uint4 A1h = *(uint4*)&A1hf, A1l = *(uint4*)&A1lf;
            int fb = ((k * 8 + s) * 8 + wn * 4) * 64 + lane * 2;
#pragma unroll
            for (int nt4 = 0; nt4 < 4; nt4++) {
                uint2 Bh = *(const uint2*)&g_wfragH[fb + nt4 * 64];
                uint2 Bl = *(const uint2*)&g_wfragL[fb + nt4 * 64];
                mma_tf32(acc[0][nt4], A0h, Bh);
                mma_tf32(acc[0][nt4], A0l, Bh);
                mma_tf32(acc[0][nt4], A0h, Bl);
                mma_tf32(acc[1][nt4], A1h, Bh);
                mma_tf32(acc[1][nt4], A1l, Bh);
                mma_tf32(acc[1][nt4], A1h, Bl);
            }
        }
    }

    // ---- epilogue: stage [o][p] in smem (pitch 132, conflict-free), coalesced stores ----
    __syncthreads();
    float* outS = sm;                // 64*132 = 8448 floats <= 13952 available
#pragma unroll
    for (int mt = 0; mt < 2; mt++) {
        int p0 = wm * 32 + mt * 16 + gid;
#pragma unroll
        for (int nt4 = 0; nt4 < 4; nt4++) {
            int n0 = (wn * 4 + nt4) * 8 + t4 * 2;
            outS[(n0 + 0) * 132 + p0]     = acc[mt][nt4][0];
            outS[(n0 + 1) * 132 + p0]     = acc[mt][nt4][1];
            outS[(n0 + 0) * 132 + p0 + 8] = acc[mt][nt4][2];
            outS[(n0 + 1) * 132 + p0 + 8] = acc[mt][nt4][3];
        }
    }
    __syncthreads();
    for (int i = t; i < 64 * 128; i += 256) {
        int o = i >> 7, pp = i & 127;
        if (pp < W_OUT) {
            float v = outS[o * 132 + pp] + bias[o];
            out[((b * C_OUT + o) * H_OUT + ho) * W_OUT + pp] = fmaxf(v, 0.f);
        }
    }
}

// ---------------- launch ----------------
extern "C" void kernel_launch(void* const* d_in, const int* in_sizes, int n_in,
                              void* d_out, int out_size) {
    const float* x      = (const float*)d_in[0];
    const float* w_off  = (const float*)d_in[1];
    const float* b_off  = (const float*)d_in[2];
    const float* weight = (const float*)d_in[3];
    const float* bias   = (const float*)d_in[4];
    float* out = (float*)d_out;
    (void)in_sizes; (void)n_in; (void)out_size;

    cudaFuncSetAttribute(k_offset_conv, cudaFuncAttributeMaxDynamicSharedMemorySize, SMEM_A);
    cudaFuncSetAttribute(k_deform_gemm, cudaFuncAttributeMaxDynamicSharedMemorySize, SMEM_B);

    k_transpose_x<<<dim3(HWIN / 32, C_IN / 32, B_N), dim3(32, 8)>>>(x);
    k_prep_w<<<(NFRAG + 255) / 256, 256>>>(w_off, weight);
    k_offset_conv<<<dim3(4, 8, B_N), 256, SMEM_A>>>(b_off);
    k_deform_gemm<<<dim3(1, H_OUT, B_N), 256, SMEM_B>>>(bias, out);
}

// round 8
// speedup vs baseline: 3.1397x; 1.0371x over previous
#include <cuda_runtime.h>
#include <math.h>
#include <stdint.h>

#define B_N   4
#define C_IN  64
#define C_OUT 64
#define H_IN  128
#define W_IN  128
#define H_OUT 126
#define W_OUT 126
#define CK    576            // 9 * 64
#define HWIN  (H_IN * W_IN)
#define HWOUT (H_OUT * W_OUT)
#define NFRAG (9 * 8 * 8 * 32 * 2)   // 36864 fragment floats

// ---------------- scratch (device globals; no allocations allowed) ----------------
__device__ __align__(16) float g_xnhwc[B_N * HWIN * C_IN];        // 16 MB
__device__ __align__(16) float g_off[B_N * 27 * HWOUT];           // ~6.9 MB
__device__ __align__(16) float g_wfragH[NFRAG];                   // tf32-hi B fragments
__device__ __align__(16) float g_wfragL[NFRAG];                   // residual B fragments
__device__ __align__(16) float g_wOffT[CK * 28];                  // [k*64+c][28] (27 padded)

__device__ __forceinline__ float tf32_hi(float a) {
    return __uint_as_float(__float_as_uint(a) & 0xFFFFE000u);
}

// ---------------- prep: NCHW -> NHWC transpose ----------------
__global__ void k_transpose_x(const float* __restrict__ x) {
    __shared__ float tile[32][33];
    int b   = blockIdx.z;
    int hw0 = blockIdx.x * 32;
    int c0  = blockIdx.y * 32;
    int tx = threadIdx.x, ty = threadIdx.y;
#pragma unroll
    for (int i = ty; i < 32; i += 8)
        tile[i][tx] = x[((size_t)(b * C_IN + c0 + i)) * HWIN + hw0 + tx];
    __syncthreads();
#pragma unroll
    for (int i = ty; i < 32; i += 8)
        g_xnhwc[((size_t)b * HWIN + hw0 + i) * C_IN + c0 + tx] = tile[tx][i];
}

// ---------------- prep: offset-weight transpose + main-weight hi/lo B-fragment pack ----------------
// B fragment (mma.m16n8k8.row.col): element e of lane = B[k=(lane&3)+4e][n=lane>>2]
// g_wfrag*[((k*8 + s)*8 + nt)*64 + lane*2 + e] = weight[o=nt*8+(lane>>2)][c=s*8+(lane&3)+4e][tap k]
__global__ void k_prep_w(const float* __restrict__ w_off, const float* __restrict__ weight) {
    int t = blockIdx.x * blockDim.x + threadIdx.x;
    if (t < CK * 28) {
        int ck = t / 28, co = t - ck * 28;
        int kk = ck >> 6, cc = ck & 63;
        g_wOffT[t] = (co < 27) ? w_off[co * CK + cc * 9 + kk] : 0.f;
    }
    if (t < NFRAG) {
        int e    = t & 1;
        int lane = (t >> 1) & 31;
        int nt   = (t >> 6) & 7;
        int s    = (t >> 9) & 7;
        int k    = t >> 12;
        int o = nt * 8 + (lane >> 2);
        int c = s * 8 + (lane & 3) + 4 * e;
        float w  = weight[o * CK + c * 9 + k];
        float wh = tf32_hi(w);
        g_wfragH[t] = wh;
        g_wfragL[t] = w - wh;
    }
}

// ---------------- offset conv: x (NHWC) * w_off -> g_off (sigmoid on ch 18..26) ----------------
#define A_PITCH 65
#define A_ROWS  18
#define A_COLS  34
#define A_NPIX  (A_ROWS * A_COLS)          // 612
#define SMEM_A  ((A_NPIX * A_PITCH + CK * 28) * 4)   // 223632 bytes

__global__ __launch_bounds__(256, 1) void k_offset_conv(const float* __restrict__ b_off) {
    extern __shared__ float sm[];
    float* patch = sm;                       // [612][65]
    float* ws    = sm + A_NPIX * A_PITCH;    // [576][28], float4-aligned rows

    int b  = blockIdx.z;
    int h0 = blockIdx.y * 16;
    int w0 = blockIdx.x * 32;
    int t  = threadIdx.x;

    for (int i = t; i < CK * 28; i += 256) ws[i] = g_wOffT[i];

    const float* xb = g_xnhwc + (size_t)b * HWIN * C_IN;
    for (int i = t; i < A_NPIX * C_IN; i += 256) {
        int c = i & 63, pix = i >> 6;
        int r = pix / A_COLS, col = pix - r * A_COLS;
        int hh = min(h0 + r,   H_IN - 1);
        int ww = min(w0 + col, W_IN - 1);
        patch[pix * A_PITCH + c] = xb[(hh * W_IN + ww) * C_IN + c];
    }
    __syncthreads();

    int tx = t & 31, ty = t >> 5;            // 8 rows x 32 cols, 2 pixels/thread
    float acc0[28], acc1[28];
#pragma unroll
    for (int j = 0; j < 28; j++) { acc0[j] = 0.f; acc1[j] = 0.f; }

#pragma unroll
    for (int ky = 0; ky < 3; ky++) {
#pragma unroll
        for (int kx = 0; kx < 3; kx++) {
            int kk = ky * 3 + kx;
            const float* p0 = &patch[((ty + ky)     * A_COLS + tx + kx) * A_PITCH];
            const float* p1 = &patch[((ty + 8 + ky) * A_COLS + tx + kx) * A_PITCH];
            const float4* wb = (const float4*)&ws[kk * 64 * 28];
#pragma unroll 2
            for (int c = 0; c < 64; c++) {
                float x0 = p0[c], x1 = p1[c];
                const float4* wv = wb + c * 7;
#pragma unroll
                for (int g = 0; g < 7; g++) {
                    float4 w4 = wv[g];
                    acc0[g*4+0] += x0 * w4.x; acc1[g*4+0] += x1 * w4.x;
                    acc0[g*4+1] += x0 * w4.y; acc1[g*4+1] += x1 * w4.y;
                    acc0[g*4+2] += x0 * w4.z; acc1[g*4+2] += x1 * w4.z;
                    acc0[g*4+3] += x0 * w4.w; acc1[g*4+3] += x1 * w4.w;
                }
            }
        }
    }

    int wo = w0 + tx;
    if (wo < W_OUT) {
        int ho0 = h0 + ty, ho1 = h0 + ty + 8;
        if (ho0 < H_OUT) {
#pragma unroll
            for (int j = 0; j < 27; j++) {
                float v = acc0[j] + b_off[j];
                if (j >= 18) v = 1.f / (1.f + expf(-v));
                g_off[((b * 27 + j) * H_OUT + ho0) * W_OUT + wo] = v;
            }
        }
        if (ho1 < H_OUT) {
#pragma unroll
            for (int j = 0; j < 27; j++) {
                float v = acc1[j] + b_off[j];
                if (j >= 18) v = 1.f / (1.f + expf(-v));
                g_off[((b * 27 + j) * H_OUT + ho1) * W_OUT + wo] = v;
            }
        }
    }
}

// ---------------- fused deform-sample + 3xTF32 MMA GEMM + bias + ReLU ----------------
// Block: 256 threads (8 warps). Tile: one output row (128 px) x 64 out channels.
// Warp tile: 32 px x 32 out = 2x4 m16n8k8 mma tiles, K=64 per tap (8 ksteps).
// Tap params computed inline in the sampling loop (g_off reads are L1 broadcasts);
// B fragments read straight from global (L1/L2-hot). S in A-fragment order with
// XOR-by-kstep swizzle. smem = 33 KB -> 4 blocks/SM at the 64-reg cap.
#define SMEM_B (8448 * 4)   // max(S 8192, epilogue 64*132) floats

__device__ __forceinline__ void mma_tf32(float* d, const uint4 a, const uint2 b) {
    asm volatile(
        "mma.sync.aligned.m16n8k8.row.col.f32.tf32.tf32.f32 "
        "{%0,%1,%2,%3},{%4,%5,%6,%7},{%8,%9},{%0,%1,%2,%3};"
        : "+f"(d[0]), "+f"(d[1]), "+f"(d[2]), "+f"(d[3])
        : "r"(a.x), "r"(a.y), "r"(a.z), "r"(a.w), "r"(b.x), "r"(b.y));
}

__global__ __launch_bounds__(256, 4) void k_deform_gemm(const float* __restrict__ bias,
                                                        float* __restrict__ out) {
    extern __shared__ float sm[];
    float* S = sm;                   // [8192] A-fragment layout

    int b  = blockIdx.z;
    int ho = blockIdx.y;
    int t  = threadIdx.x;

    const float* xb = g_xnhwc + b * (HWIN * C_IN);
    int obase = ((b * 27) * H_OUT + ho) * W_OUT;

    int lane = t & 31;
    int wrp  = t >> 5;
    int wm   = wrp & 3;              // M-tile: pixels [wm*32, wm*32+32)
    int wn   = wrp >> 2;             // N-tile: outputs [wn*32, wn*32+32)
    int t4   = lane & 3, gid = lane >> 2;

    float acc[2][4][4];              // [mt][nt4][reg]
#pragma unroll
    for (int i = 0; i < 2; i++)
#pragma unroll
        for (int j = 0; j < 4; j++)
#pragma unroll
            for (int r = 0; r < 4; r++) acc[i][j][r] = 0.f;

    for (int k = 0; k < 9; k++) {
        int kh = k / 3, kw = k - kh * 3;

        // ---- bilinear sampling into A-fragment layout (params inline) ----
#pragma unroll
        for (int it = 0; it < 8; it++) {
            int j  = t + it * 256;
            int cg = j & 15;             // channel group (cq = cg*4)
            int p  = j >> 4;             // pixel 0..127
            int cq = cg << 2;
            int wo = min(p, W_OUT - 1);
            // interleaved layout: off_y[k] = ch 2k, off_x[k] = ch 2k+1, mask = ch 18+k
            float oy = g_off[obase + wo + (2 * k)     * HWOUT];
            float ox = g_off[obase + wo + (2 * k + 1) * HWOUT];
            float m  = g_off[obase + wo + (18 + k)    * HWOUT];
            float ys = (float)(ho + kh) + oy;
            float xs = (float)(wo + kw) + ox;
            float yf = floorf(ys), xf = floorf(xs);
            float wy = ys - yf, wx = xs - xf;
            int y0 = (int)yf, x0 = (int)xf;
            float w00 = (1.f - wy) * (1.f - wx) * m;
            float w01 = (1.f - wy) * wx * m;
            float w10 = wy * (1.f - wx) * m;
            float w11 = wy * wx * m;
            int y1 = y0 + 1, x1 = x0 + 1;
            float rv[4] = {0.f, 0.f, 0.f, 0.f};
            if ((unsigned)y0 < (unsigned)H_IN) {
                const float* row = xb + (y0 * W_IN) * C_IN + cq;
                if ((unsigned)x0 < (unsigned)W_IN) {
                    float4 v = *(const float4*)(row + x0 * C_IN);
                    rv[0] += w00 * v.x; rv[1] += w00 * v.y; rv[2] += w00 * v.z; rv[3] += w00 * v.w;
                }
                if ((unsigned)x1 < (unsigned)W_IN) {
                    float4 v = *(const float4*)(row + x1 * C_IN);
                    rv[0] += w01 * v.x; rv[1] += w01 * v.y; rv[2] += w01 * v.z; rv[3] += w01 * v.w;
                }
            }
            if ((unsigned)y1 < (unsigned)H_IN) {
                const float* row = xb + (y1 * W_IN) * C_IN + cq;
                if ((unsigned)x0 < (unsigned)W_IN) {
                    float4 v = *(const float4*)(row + x0 * C_IN);
                    rv[0] += w10 * v.x; rv[1] += w10 * v.y; rv[2] += w10 * v.z; rv[3] += w10 * v.w;
                }
                if ((unsigned)x1 < (unsigned)W_IN) {
                    float4 v = *(const float4*)(row + x1 * C_IN);
                    rv[0] += w11 * v.x; rv[1] += w11 * v.y; rv[2] += w11 * v.z; rv[3] += w11 * v.w;
                }
            }
            // scatter into A-fragment slots (XOR-by-s swizzle)
            int s    = cg >> 1;
            int reg  = ((p >> 3) & 1) + 2 * (cg & 1);       // h + 2*half
            int base = (((p >> 4) * 8) + s) * 128 + reg;    // (wm*2+f) = p>>4
            int gl4  = (p & 7) << 2;                        // gid*4
#pragma unroll
            for (int u = 0; u < 4; u++)
                S[base + (((gl4 | u) ^ s) << 2)] = rv[u];
        }
        __syncthreads();

        // ---- 3xTF32 MMA: K=64 for this tap, 8 ksteps; mt-outer keeps regs lean ----
#pragma unroll
        for (int s = 0; s < 8; s++) {
            int aoff = (lane ^ s) << 2;
            int fb   = ((k * 8 + s) * 8 + wn * 4) * 64 + lane * 2;
#pragma unroll
            for (int mt = 0; mt < 2; mt++) {
                float4 Af = *(const float4*)&S[((wm * 2 + mt) * 8 + s) * 128 + aoff];
                float4 Ahf, Alf;
                Ahf.x = tf32_hi(Af.x); Alf.x = Af.x - Ahf.x;
                Ahf.y = tf32_hi(Af.y); Alf.y = Af.y - Ahf.y;
                Ahf.z = tf32_hi(Af.z); Alf.z = Af.z - Ahf.z;
                Ahf.w = tf32_hi(Af.w); Alf.w = Af.w - Ahf.w;
                uint4 Ah = *(uint4*)&Ahf, Al = *(uint4*)&Alf;
#pragma unroll
                for (int nt4 = 0; nt4 < 4; nt4++) {
                    uint2 Bh = *(const uint2*)&g_wfragH[fb + nt4 * 64];
                    uint2 Bl = *(const uint2*)&g_wfragL[fb + nt4 * 64];
                    mma_tf32(acc[mt][nt4], Ah, Bh);
                    mma_tf32(acc[mt][nt4], Al, Bh);
                    mma_tf32(acc[mt][nt4], Ah, Bl);
                }
            }
        }
        __syncthreads();             // S free for next tap's sampling
    }

    // ---- epilogue: stage [o][p] in smem (pitch 132, conflict-free), coalesced stores ----
    float* outS = sm;
#pragma unroll
    for (int mt = 0; mt < 2; mt++) {
        int p0 = wm * 32 + mt * 16 + gid;
#pragma unroll
        for (int nt4 = 0; nt4 < 4; nt4++) {
            int n0 = (wn * 4 + nt4) * 8 + t4 * 2;
            outS[(n0 + 0) * 132 + p0]     = acc[mt][nt4][0];
            outS[(n0 + 1) * 132 + p0]     = acc[mt][nt4][1];
            outS[(n0 + 0) * 132 + p0 + 8] = acc[mt][nt4][2];
            outS[(n0 + 1) * 132 + p0 + 8] = acc[mt][nt4][3];
        }
    }
    __syncthreads();
    for (int i = t; i < 64 * 128; i += 256) {
        int o = i >> 7, pp = i & 127;
        if (pp < W_OUT) {
            float v = outS[o * 132 + pp] + bias[o];
            out[((b * C_OUT + o) * H_OUT + ho) * W_OUT + pp] = fmaxf(v, 0.f);
        }
    }
}

// ---------------- launch ----------------
extern "C" void kernel_launch(void* const* d_in, const int* in_sizes, int n_in,
                              void* d_out, int out_size) {
    const float* x      = (const float*)d_in[0];
    const float* w_off  = (const float*)d_in[1];
    const float* b_off  = (const float*)d_in[2];
    const float* weight = (const float*)d_in[3];
    const float* bias   = (const float*)d_in[4];
    float* out = (float*)d_out;
    (void)in_sizes; (void)n_in; (void)out_size;

    cudaFuncSetAttribute(k_offset_conv, cudaFuncAttributeMaxDynamicSharedMemorySize, SMEM_A);
    cudaFuncSetAttribute(k_deform_gemm, cudaFuncAttributeMaxDynamicSharedMemorySize, SMEM_B);

    k_transpose_x<<<dim3(HWIN / 32, C_IN / 32, B_N), dim3(32, 8)>>>(x);
    k_prep_w<<<(NFRAG + 255) / 256, 256>>>(w_off, weight);
    k_offset_conv<<<dim3(4, 8, B_N), 256, SMEM_A>>>(b_off);
    k_deform_gemm<<<dim3(1, H_OUT, B_N), 256, SMEM_B>>>(bias, out);
}